// round 1
// baseline (speedup 1.0000x reference)
#include <cuda_runtime.h>

#define BETA_C (8.0f / 3.0f)

__device__ __forceinline__ void lorenz_step(float yin0, float yin1, float yin2,
                                            float& o0, float& o1, float& o2) {
    const float h  = 0.01f;
    const float c1 = 0.5f * h;            // a0*h
    const float c2 = h * h / 6.0f;        // a1*h^2 == a2*h^2
    const float c3 = h * h * h / 8.0f;    // a4*h^3 (=3/24)
    const float c4 = h * h * h / 24.0f;   // a5*h^3 == a6*h^3

    float y0 = 10.0f * yin0;
    float y1 = 10.0f * yin1;
    float y2 = 10.0f * yin2;

    // f(y)
    float f0 = 10.0f * y1 - 10.0f * y0;
    float f1 = 28.0f * y0 - y0 * y2 - y1;
    float f2 = y0 * y1 - BETA_C * y2;

    float j00 = 28.0f - y2;  // reused jac coefficient

    // dff = J f
    float dff0 = 10.0f * f1 - 10.0f * f0;
    float dff1 = j00 * f0 - f1 - y0 * f2;
    float dff2 = y1 * f0 + y0 * f1 - BETA_C * f2;

    // dfdff = J dff
    float dfdff0 = 10.0f * dff1 - 10.0f * dff0;
    float dfdff1 = j00 * dff0 - dff1 - y0 * dff2;
    float dfdff2 = y1 * dff0 + y0 * dff1 - BETA_C * dff2;

    // ddfff = ddf(f,f)   (component 0 is zero)
    float ddfff1 = -2.0f * f0 * f2;
    float ddfff2 =  2.0f * f0 * f1;

    // ddfdfff = ddf(dff,f)
    float ddfdfff1 = -dff0 * f2 - dff2 * f0;
    float ddfdfff2 =  dff0 * f1 + dff1 * f0;

    // dfddfff = J ddfff, with the reference's y0*f1 quirk in component 2
    float dfddfff0 = 10.0f * ddfff1;                    // -10*0 + 10*ddfff1
    float dfddfff1 = -ddfff1 - y0 * ddfff2;             // j00*0 - ddfff1 - y0*ddfff2
    float dfddfff2 = y0 * f1 - BETA_C * ddfff2;         // y1*0 + y0*f1 - B*ddfff2

    // dfdfdff = J dfdff
    float dfdfdff0 = 10.0f * dfdff1 - 10.0f * dfdff0;
    float dfdfdff1 = j00 * dfdff0 - dfdff1 - y0 * dfdff2;
    float dfdfdff2 = y1 * dfdff0 + y0 * dfdff1 - BETA_C * dfdff2;

    o0 = (f0 + c1 * dff0 + c2 * dfdff0
             + c4 * (dfddfff0 + dfdfdff0)) * 0.1f;
    o1 = (f1 + c1 * dff1 + c2 * (ddfff1 + dfdff1)
             + c3 * ddfdfff1 + c4 * (dfddfff1 + dfdfdff1)) * 0.1f;
    o2 = (f2 + c1 * dff2 + c2 * (ddfff2 + dfdff2)
             + c3 * ddfdfff2 + c4 * (dfddfff2 + dfdfdff2)) * 0.1f;
}

// Each thread processes 4 triples = 12 floats = 3 coalesced float4 loads/stores.
__global__ void IE_LS_kernel(const float4* __restrict__ in,
                             float4* __restrict__ out,
                             int n_groups) {
    int g = blockIdx.x * blockDim.x + threadIdx.x;
    if (g >= n_groups) return;

    float4 a = in[3 * g + 0];
    float4 b = in[3 * g + 1];
    float4 c = in[3 * g + 2];

    float v[12] = {a.x, a.y, a.z, a.w, b.x, b.y, b.z, b.w, c.x, c.y, c.z, c.w};
    float r[12];

#pragma unroll
    for (int t = 0; t < 4; t++) {
        lorenz_step(v[3 * t + 0], v[3 * t + 1], v[3 * t + 2],
                    r[3 * t + 0], r[3 * t + 1], r[3 * t + 2]);
    }

    out[3 * g + 0] = make_float4(r[0], r[1], r[2], r[3]);
    out[3 * g + 1] = make_float4(r[4], r[5], r[6], r[7]);
    out[3 * g + 2] = make_float4(r[8], r[9], r[10], r[11]);
}

// Tail kernel for any leftover triples (not expected for this shape, but safe).
__global__ void IE_LS_tail_kernel(const float* __restrict__ in,
                                  float* __restrict__ out,
                                  int start_triple, int n_triples) {
    int t = start_triple + blockIdx.x * blockDim.x + threadIdx.x;
    if (t >= n_triples) return;
    float o0, o1, o2;
    lorenz_step(in[3 * t], in[3 * t + 1], in[3 * t + 2], o0, o1, o2);
    out[3 * t] = o0; out[3 * t + 1] = o1; out[3 * t + 2] = o2;
}

extern "C" void kernel_launch(void* const* d_in, const int* in_sizes, int n_in,
                              void* d_out, int out_size) {
    const float* in = (const float*)d_in[0];
    float* out = (float*)d_out;
    int n_elems = in_sizes[0];          // 12582912 = 4194304 * 3
    int n_triples = n_elems / 3;
    int n_groups = n_triples / 4;       // 4 triples per thread

    if (n_groups > 0) {
        int threads = 256;
        int blocks = (n_groups + threads - 1) / threads;
        IE_LS_kernel<<<blocks, threads>>>((const float4*)in, (float4*)out, n_groups);
    }
    int done = n_groups * 4;
    int rem = n_triples - done;
    if (rem > 0) {
        IE_LS_tail_kernel<<<(rem + 255) / 256, 256>>>(in, out, done, n_triples);
    }
}

// round 5
// speedup vs baseline: 1.0125x; 1.0125x over previous
#include <cuda_runtime.h>

#define BETA_C (8.0f / 3.0f)

__device__ __forceinline__ void lorenz_step(float yin0, float yin1, float yin2,
                                            float& o0, float& o1, float& o2) {
    const float h  = 0.01f;
    const float c1 = 0.5f * h;            // a0*h
    const float c2 = h * h / 6.0f;        // a1*h^2 == a2*h^2
    const float c3 = h * h * h / 8.0f;    // a4*h^3 (=3/24)
    const float c4 = h * h * h / 24.0f;   // a5*h^3 == a6*h^3

    float y0 = 10.0f * yin0;
    float y1 = 10.0f * yin1;
    float y2 = 10.0f * yin2;

    // f(y)
    float f0 = 10.0f * y1 - 10.0f * y0;
    float f1 = 28.0f * y0 - y0 * y2 - y1;
    float f2 = y0 * y1 - BETA_C * y2;

    float j00 = 28.0f - y2;  // reused jac coefficient

    // dff = J f
    float dff0 = 10.0f * f1 - 10.0f * f0;
    float dff1 = j00 * f0 - f1 - y0 * f2;
    float dff2 = y1 * f0 + y0 * f1 - BETA_C * f2;

    // dfdff = J dff
    float dfdff0 = 10.0f * dff1 - 10.0f * dff0;
    float dfdff1 = j00 * dff0 - dff1 - y0 * dff2;
    float dfdff2 = y1 * dff0 + y0 * dff1 - BETA_C * dff2;

    // ddfff = ddf(f,f)   (component 0 is zero)
    float ddfff1 = -2.0f * f0 * f2;
    float ddfff2 =  2.0f * f0 * f1;

    // ddfdfff = ddf(dff,f)
    float ddfdfff1 = -dff0 * f2 - dff2 * f0;
    float ddfdfff2 =  dff0 * f1 + dff1 * f0;

    // dfddfff = J ddfff, with the reference's y0*f1 quirk in component 2
    float dfddfff0 = 10.0f * ddfff1;
    float dfddfff1 = -ddfff1 - y0 * ddfff2;
    float dfddfff2 = y0 * f1 - BETA_C * ddfff2;

    // dfdfdff = J dfdff
    float dfdfdff0 = 10.0f * dfdff1 - 10.0f * dfdff0;
    float dfdfdff1 = j00 * dfdff0 - dfdff1 - y0 * dfdff2;
    float dfdfdff2 = y1 * dfdff0 + y0 * dfdff1 - BETA_C * dfdff2;

    o0 = (f0 + c1 * dff0 + c2 * dfdff0
             + c4 * (dfddfff0 + dfdfdff0)) * 0.1f;
    o1 = (f1 + c1 * dff1 + c2 * (ddfff1 + dfdff1)
             + c3 * ddfdfff1 + c4 * (dfddfff1 + dfdfdff1)) * 0.1f;
    o2 = (f2 + c1 * dff2 + c2 * (ddfff2 + dfdff2)
             + c3 * ddfdfff2 + c4 * (dfddfff2 + dfdfdff2)) * 0.1f;
}

// Block of 256 threads handles 1024 triples = 3072 floats = 768 float4s.
// All global accesses are unit-stride across lanes (4 lines / LDG.128).
// Shared memory does the AoS<->per-thread-triple transpose.
__global__ void __launch_bounds__(256) IE_LS_kernel(
    const float4* __restrict__ in, float4* __restrict__ out) {
    __shared__ float4 s[768];

    const int t = threadIdx.x;
    const long long base = (long long)blockIdx.x * 768;

    // Phase A: coalesced global -> smem
#pragma unroll
    for (int k = 0; k < 3; k++)
        s[k * 256 + t] = in[base + k * 256 + t];
    __syncthreads();

    // Phase B: each thread owns triples 4t..4t+3 = floats 12t..12t+11
    // LDS.128 at 48B inter-lane stride: conflict-free (distinct banks per phase).
    float4* sv = (float4*)s;
    float4 a = sv[3 * t + 0];
    float4 b = sv[3 * t + 1];
    float4 c = sv[3 * t + 2];

    float v[12] = {a.x, a.y, a.z, a.w, b.x, b.y, b.z, b.w, c.x, c.y, c.z, c.w};
    float r[12];
#pragma unroll
    for (int q = 0; q < 4; q++) {
        lorenz_step(v[3 * q + 0], v[3 * q + 1], v[3 * q + 2],
                    r[3 * q + 0], r[3 * q + 1], r[3 * q + 2]);
    }

    // Write results back to the same slots (same-thread: no sync needed first)
    sv[3 * t + 0] = make_float4(r[0], r[1], r[2], r[3]);
    sv[3 * t + 1] = make_float4(r[4], r[5], r[6], r[7]);
    sv[3 * t + 2] = make_float4(r[8], r[9], r[10], r[11]);
    __syncthreads();

    // Phase C: coalesced smem -> global
#pragma unroll
    for (int k = 0; k < 3; k++)
        out[base + k * 256 + t] = s[k * 256 + t];
}

// Tail kernel for leftover triples (not hit for the bench shape).
__global__ void IE_LS_tail_kernel(const float* __restrict__ in,
                                  float* __restrict__ out,
                                  int start_triple, int n_triples) {
    int t = start_triple + blockIdx.x * blockDim.x + threadIdx.x;
    if (t >= n_triples) return;
    float o0, o1, o2;
    lorenz_step(in[3 * t], in[3 * t + 1], in[3 * t + 2], o0, o1, o2);
    out[3 * t] = o0; out[3 * t + 1] = o1; out[3 * t + 2] = o2;
}

extern "C" void kernel_launch(void* const* d_in, const int* in_sizes, int n_in,
                              void* d_out, int out_size) {
    const float* in = (const float*)d_in[0];
    float* out = (float*)d_out;
    int n_elems = in_sizes[0];            // 12582912 = 4194304 * 3
    int n_triples = n_elems / 3;
    int n_blocks = n_triples / 1024;      // 1024 triples per 256-thread block

    if (n_blocks > 0) {
        IE_LS_kernel<<<n_blocks, 256>>>((const float4*)in, (float4*)out);
    }
    int done = n_blocks * 1024;
    int rem = n_triples - done;
    if (rem > 0) {
        IE_LS_tail_kernel<<<(rem + 255) / 256, 256>>>(in, out, done, n_triples);
    }
}

// round 6
// speedup vs baseline: 1.1346x; 1.1206x over previous
#include <cuda_runtime.h>

#define BETA_C (8.0f / 3.0f)

__device__ __forceinline__ void lorenz_step(float yin0, float yin1, float yin2,
                                            float& o0, float& o1, float& o2) {
    const float h  = 0.01f;
    const float c1 = 0.5f * h;            // a0*h
    const float c2 = h * h / 6.0f;        // a1*h^2 == a2*h^2
    const float c3 = h * h * h / 8.0f;    // a4*h^3 (=3/24)
    const float c4 = h * h * h / 24.0f;   // a5*h^3 == a6*h^3

    float y0 = 10.0f * yin0;
    float y1 = 10.0f * yin1;
    float y2 = 10.0f * yin2;

    // f(y)
    float f0 = 10.0f * y1 - 10.0f * y0;
    float f1 = 28.0f * y0 - y0 * y2 - y1;
    float f2 = y0 * y1 - BETA_C * y2;

    float j00 = 28.0f - y2;  // reused jac coefficient

    // dff = J f
    float dff0 = 10.0f * f1 - 10.0f * f0;
    float dff1 = j00 * f0 - f1 - y0 * f2;
    float dff2 = y1 * f0 + y0 * f1 - BETA_C * f2;

    // dfdff = J dff
    float dfdff0 = 10.0f * dff1 - 10.0f * dff0;
    float dfdff1 = j00 * dff0 - dff1 - y0 * dff2;
    float dfdff2 = y1 * dff0 + y0 * dff1 - BETA_C * dff2;

    // ddfff = ddf(f,f)   (component 0 is zero)
    float ddfff1 = -2.0f * f0 * f2;
    float ddfff2 =  2.0f * f0 * f1;

    // ddfdfff = ddf(dff,f)
    float ddfdfff1 = -dff0 * f2 - dff2 * f0;
    float ddfdfff2 =  dff0 * f1 + dff1 * f0;

    // dfddfff = J ddfff, with the reference's y0*f1 quirk in component 2
    float dfddfff0 = 10.0f * ddfff1;
    float dfddfff1 = -ddfff1 - y0 * ddfff2;
    float dfddfff2 = y0 * f1 - BETA_C * ddfff2;

    // dfdfdff = J dfdff
    float dfdfdff0 = 10.0f * dfdff1 - 10.0f * dfdff0;
    float dfdfdff1 = j00 * dfdff0 - dfdff1 - y0 * dfdff2;
    float dfdfdff2 = y1 * dfdff0 + y0 * dfdff1 - BETA_C * dfdff2;

    o0 = (f0 + c1 * dff0 + c2 * dfdff0
             + c4 * (dfddfff0 + dfdfdff0)) * 0.1f;
    o1 = (f1 + c1 * dff1 + c2 * (ddfff1 + dfdff1)
             + c3 * ddfdfff1 + c4 * (dfddfff1 + dfdfdff1)) * 0.1f;
    o2 = (f2 + c1 * dff2 + c2 * (ddfff2 + dfdff2)
             + c3 * ddfdfff2 + c4 * (dfddfff2 + dfdfdff2)) * 0.1f;
}

struct F12 { float4 a, b, c; };

// Warp-autonomous tiles: each warp owns 96 float4s (128 triples) of smem.
// Only __syncwarp needed -> warps of a CTA slide out of phase, overlapping
// loads/compute/stores across the SM instead of barrier-coupled bursts.
// In-place compute keeps live registers to ~12 data + temps (no spills).
__global__ void IE_LS_kernel(const float4* __restrict__ in,
                             float4* __restrict__ out) {
    __shared__ float4 s[768];   // 8 warps * 96

    const int lane = threadIdx.x & 31;
    const int warp = threadIdx.x >> 5;
    float4* sw = s + warp * 96;
    const long long gbase = (long long)blockIdx.x * 768 + warp * 96;

    // Phase A: coalesced global -> warp-local smem (512B per LDG per warp)
#pragma unroll
    for (int k = 0; k < 3; k++)
        sw[lane + 32 * k] = in[gbase + lane + 32 * k];
    __syncwarp();

    // Phase B: lane owns float4s 3*lane .. 3*lane+2 (4 triples).
    // LDS.128 at 48B stride: banks 12*l mod 32 distinct per 8-lane phase.
    F12 d;
    d.a = sw[3 * lane + 0];
    d.b = sw[3 * lane + 1];
    d.c = sw[3 * lane + 2];
    float* p = (float*)&d;
#pragma unroll
    for (int q = 0; q < 4; q++) {
        lorenz_step(p[3 * q + 0], p[3 * q + 1], p[3 * q + 2],
                    p[3 * q + 0], p[3 * q + 1], p[3 * q + 2]);
    }
    sw[3 * lane + 0] = d.a;
    sw[3 * lane + 1] = d.b;
    sw[3 * lane + 2] = d.c;
    __syncwarp();

    // Phase C: coalesced warp-local smem -> global
#pragma unroll
    for (int k = 0; k < 3; k++)
        out[gbase + lane + 32 * k] = sw[lane + 32 * k];
}

// Tail kernel for leftover triples (not hit for the bench shape).
__global__ void IE_LS_tail_kernel(const float* __restrict__ in,
                                  float* __restrict__ out,
                                  int start_triple, int n_triples) {
    int t = start_triple + blockIdx.x * blockDim.x + threadIdx.x;
    if (t >= n_triples) return;
    float o0, o1, o2;
    lorenz_step(in[3 * t], in[3 * t + 1], in[3 * t + 2], o0, o1, o2);
    out[3 * t] = o0; out[3 * t + 1] = o1; out[3 * t + 2] = o2;
}

extern "C" void kernel_launch(void* const* d_in, const int* in_sizes, int n_in,
                              void* d_out, int out_size) {
    const float* in = (const float*)d_in[0];
    float* out = (float*)d_out;
    int n_elems = in_sizes[0];            // 12582912 = 4194304 * 3
    int n_triples = n_elems / 3;
    int n_blocks = n_triples / 1024;      // 1024 triples per 256-thread block

    if (n_blocks > 0) {
        IE_LS_kernel<<<n_blocks, 256>>>((const float4*)in, (float4*)out);
    }
    int done = n_blocks * 1024;
    int rem = n_triples - done;
    if (rem > 0) {
        IE_LS_tail_kernel<<<(rem + 255) / 256, 256>>>(in, out, done, n_triples);
    }
}